// round 4
// baseline (speedup 1.0000x reference)
#include <cuda_runtime.h>
#include <cuda_bf16.h>
#include <cstdint>

// ---------------------------------------------------------------------------
// SimpleGCN R4: CSR-gather aggregation (atomic-free) instead of edge scatter.
//
// Pipeline (fp32):
//   0. detect edge_index dtype (int32 under default JAX despite jnp.int64)
//   1. zero deg
//   2. edge_prep: decode edges + in-degree histogram
//   3. scan: row_ptr = exclusive_scan(deg); cursor = row_ptr; dinv = rsqrt(deg+1)
//   4. csr_fill: counting-sort edge srcs by dst
//   5. gemm1: h1 = x @ W1
//   6. agg1: a1[r] = sum_{s in inedges(r)} h1[s]*dinv[s]*dinv[r] + h1[r]*dinv[r]^2
//   7. gemm2: h2 = relu(a1 + b1) @ W2
//   8. agg2: a2[r] = sum h2[s]*norm + h2[r]*dinv[r]^2
//   9. finalize: out = log_softmax(a2 + b2)
// ---------------------------------------------------------------------------

#define NMAX 100000
#define EMAX 1600000
#define F_IN 128
#define F_MID 128
#define F_OUT 64

__device__ __align__(16) int   g_src[EMAX];
__device__ __align__(16) int   g_dst[EMAX];
__device__ __align__(16) int   g_csrc[EMAX];      // CSR: src ids sorted by dst
__device__ __align__(16) int   g_deg[NMAX];
__device__ __align__(16) int   g_rowptr[NMAX + 1];
__device__ __align__(16) int   g_cursor[NMAX];
__device__ __align__(16) float g_dinv[NMAX];
__device__ __align__(16) float g_h1[(size_t)NMAX * F_MID];
__device__ __align__(16) float g_a1[(size_t)NMAX * F_MID];
__device__ __align__(16) float g_h2[(size_t)NMAX * F_OUT];
__device__ __align__(16) float g_a2[(size_t)NMAX * F_OUT];
__device__ int g_is64;

// ---------------------------------------------------------------------------
// 0. dtype detect: int64 node ids < 2^31 -> every odd int32 word is zero.
// ---------------------------------------------------------------------------
__global__ void detect_kernel(const int* __restrict__ ei32) {
    if (threadIdx.x == 0 && blockIdx.x == 0) {
        int allzero = 1;
        for (int i = 0; i < 64; i++)
            if (ei32[2 * i + 1] != 0) { allzero = 0; break; }
        g_is64 = allzero;
    }
}

// ---------------------------------------------------------------------------
// 1. zero deg
// ---------------------------------------------------------------------------
__global__ void zero_deg_kernel(int N) {
    int i = blockIdx.x * blockDim.x + threadIdx.x;
    if (i < N) g_deg[i] = 0;
}

// ---------------------------------------------------------------------------
// 2. edge decode + degree histogram
// ---------------------------------------------------------------------------
__global__ void edge_prep_kernel(const void* __restrict__ ei_raw, int E, int N) {
    const int is64 = g_is64;
    const int stride = gridDim.x * blockDim.x;
    const int* __restrict__ p32 = (const int*)ei_raw;
    const long long* __restrict__ p64 = (const long long*)ei_raw;
    for (int e = blockIdx.x * blockDim.x + threadIdx.x; e < E; e += stride) {
        int s, d;
        if (is64) {
            s = (int)p64[e];
            d = (int)p64[(size_t)E + e];
        } else {
            s = p32[e];
            d = p32[(size_t)E + e];
        }
        s = min(max(s, 0), N - 1);
        d = min(max(d, 0), N - 1);
        g_src[e] = s;
        g_dst[e] = d;
        atomicAdd(&g_deg[d], 1);
    }
}

// ---------------------------------------------------------------------------
// 3. single-block exclusive scan of deg -> row_ptr, cursor; dinv.
// ---------------------------------------------------------------------------
__global__ void scan_kernel(int N) {
    __shared__ int partial[1024];
    int tid = threadIdx.x;
    int chunk = (N + 1023) / 1024;
    int base = tid * chunk;
    int lim = min(base + chunk, N);

    int sum = 0;
    for (int i = base; i < lim; i++) sum += g_deg[i];
    partial[tid] = sum;
    __syncthreads();

    // inclusive Hillis-Steele scan over 1024 partials
    for (int off = 1; off < 1024; off <<= 1) {
        int v = 0;
        if (tid >= off) v = partial[tid - off];
        __syncthreads();
        if (tid >= off) partial[tid] += v;
        __syncthreads();
    }

    int run = (tid > 0) ? partial[tid - 1] : 0;   // exclusive prefix
    for (int i = base; i < lim; i++) {
        int dg = g_deg[i];
        g_rowptr[i] = run;
        g_cursor[i] = run;
        g_dinv[i] = rsqrtf((float)(dg + 1));
        run += dg;
    }
    if (tid == 1023) g_rowptr[N] = partial[1023];
}

// ---------------------------------------------------------------------------
// 4. counting-sort fill: csr_src grouped by dst
// ---------------------------------------------------------------------------
__global__ void csr_fill_kernel(int E) {
    int stride = gridDim.x * blockDim.x;
    for (int e = blockIdx.x * blockDim.x + threadIdx.x; e < E; e += stride) {
        int d = g_dst[e];
        int pos = atomicAdd(&g_cursor[d], 1);
        g_csrc[pos] = g_src[e];
    }
}

// ---------------------------------------------------------------------------
// 5. GEMM1: g_h1 = x @ W1   (N x 128) @ (128 x 128)
// ---------------------------------------------------------------------------
__global__ void gemm1_kernel(const float* __restrict__ X,
                             const float* __restrict__ W, int N) {
    __shared__ float xs[64][64];
    __shared__ float ws[64][64];
    int tid = threadIdx.x;
    int tx = tid & 15;
    int ty = tid >> 4;
    int row0 = blockIdx.x * 64;
    int col0 = blockIdx.y * 64;

    float acc[4][4];
#pragma unroll
    for (int i = 0; i < 4; i++)
#pragma unroll
        for (int j = 0; j < 4; j++) acc[i][j] = 0.f;

    for (int k0 = 0; k0 < F_IN; k0 += 64) {
#pragma unroll
        for (int i = 0; i < 4; i++) {
            int t = tid + i * 256;
            int r = t >> 4;
            int c4 = t & 15;
            float4 v = make_float4(0.f, 0.f, 0.f, 0.f);
            int gr = row0 + r;
            if (gr < N)
                v = *reinterpret_cast<const float4*>(&X[(size_t)gr * F_IN + k0 + c4 * 4]);
            *reinterpret_cast<float4*>(&xs[r][c4 * 4]) = v;
        }
#pragma unroll
        for (int i = 0; i < 4; i++) {
            int t = tid + i * 256;
            int r = t >> 4;
            int c4 = t & 15;
            float4 v = *reinterpret_cast<const float4*>(&W[(size_t)(k0 + r) * F_MID + col0 + c4 * 4]);
            *reinterpret_cast<float4*>(&ws[r][c4 * 4]) = v;
        }
        __syncthreads();
#pragma unroll 16
        for (int k = 0; k < 64; k++) {
            float4 w = *reinterpret_cast<float4*>(&ws[k][tx * 4]);
            float x0 = xs[ty * 4 + 0][k];
            float x1 = xs[ty * 4 + 1][k];
            float x2 = xs[ty * 4 + 2][k];
            float x3 = xs[ty * 4 + 3][k];
            acc[0][0] += x0 * w.x; acc[0][1] += x0 * w.y; acc[0][2] += x0 * w.z; acc[0][3] += x0 * w.w;
            acc[1][0] += x1 * w.x; acc[1][1] += x1 * w.y; acc[1][2] += x1 * w.z; acc[1][3] += x1 * w.w;
            acc[2][0] += x2 * w.x; acc[2][1] += x2 * w.y; acc[2][2] += x2 * w.z; acc[2][3] += x2 * w.w;
            acc[3][0] += x3 * w.x; acc[3][1] += x3 * w.y; acc[3][2] += x3 * w.z; acc[3][3] += x3 * w.w;
        }
        __syncthreads();
    }
#pragma unroll
    for (int i = 0; i < 4; i++) {
        int gr = row0 + ty * 4 + i;
        if (gr < N) {
            float4 v = make_float4(acc[i][0], acc[i][1], acc[i][2], acc[i][3]);
            *reinterpret_cast<float4*>(&g_h1[(size_t)gr * F_MID + col0 + tx * 4]) = v;
        }
    }
}

// ---------------------------------------------------------------------------
// 6. agg1: warp per dst row, register accumulation, includes self-loop.
// ---------------------------------------------------------------------------
__global__ void agg1_kernel(int N) {
    int lane = threadIdx.x & 31;
    int warp = (blockIdx.x * blockDim.x + threadIdx.x) >> 5;
    int nwarps = (gridDim.x * blockDim.x) >> 5;
    for (int r = warp; r < N; r += nwarps) {
        float dr = g_dinv[r];
        size_t rbase = (size_t)r * F_MID + lane * 4;
        // self-loop term
        float4 acc = *reinterpret_cast<const float4*>(&g_h1[rbase]);
        float d2 = dr * dr;
        acc.x *= d2; acc.y *= d2; acc.z *= d2; acc.w *= d2;

        int beg = g_rowptr[r];
        int end = g_rowptr[r + 1];
        int e = beg;
        for (; e + 1 < end; e += 2) {
            int s0 = g_csrc[e];
            int s1 = g_csrc[e + 1];
            float n0 = g_dinv[s0] * dr;
            float n1 = g_dinv[s1] * dr;
            float4 v0 = *reinterpret_cast<const float4*>(&g_h1[(size_t)s0 * F_MID + lane * 4]);
            float4 v1 = *reinterpret_cast<const float4*>(&g_h1[(size_t)s1 * F_MID + lane * 4]);
            acc.x += v0.x * n0 + v1.x * n1;
            acc.y += v0.y * n0 + v1.y * n1;
            acc.z += v0.z * n0 + v1.z * n1;
            acc.w += v0.w * n0 + v1.w * n1;
        }
        if (e < end) {
            int s0 = g_csrc[e];
            float n0 = g_dinv[s0] * dr;
            float4 v0 = *reinterpret_cast<const float4*>(&g_h1[(size_t)s0 * F_MID + lane * 4]);
            acc.x += v0.x * n0;
            acc.y += v0.y * n0;
            acc.z += v0.z * n0;
            acc.w += v0.w * n0;
        }
        *reinterpret_cast<float4*>(&g_a1[rbase]) = acc;
    }
}

// ---------------------------------------------------------------------------
// 7. GEMM2: g_h2 = relu(a1 + b1) @ W2    (a1 already has self-loop folded in)
// ---------------------------------------------------------------------------
__global__ void gemm2_kernel(const float* __restrict__ W,
                             const float* __restrict__ b1, int N) {
    __shared__ float xs[64][64];
    __shared__ float ws[64][64];
    int tid = threadIdx.x;
    int tx = tid & 15;
    int ty = tid >> 4;
    int row0 = blockIdx.x * 64;

    float acc[4][4];
#pragma unroll
    for (int i = 0; i < 4; i++)
#pragma unroll
        for (int j = 0; j < 4; j++) acc[i][j] = 0.f;

    for (int k0 = 0; k0 < F_MID; k0 += 64) {
#pragma unroll
        for (int i = 0; i < 4; i++) {
            int t = tid + i * 256;
            int r = t >> 4;
            int c4 = t & 15;
            float4 v = make_float4(0.f, 0.f, 0.f, 0.f);
            int gr = row0 + r;
            if (gr < N) {
                size_t off = (size_t)gr * F_MID + k0 + c4 * 4;
                float4 a = *reinterpret_cast<const float4*>(&g_a1[off]);
                float4 b = *reinterpret_cast<const float4*>(&b1[k0 + c4 * 4]);
                v.x = fmaxf(a.x + b.x, 0.f);
                v.y = fmaxf(a.y + b.y, 0.f);
                v.z = fmaxf(a.z + b.z, 0.f);
                v.w = fmaxf(a.w + b.w, 0.f);
            }
            *reinterpret_cast<float4*>(&xs[r][c4 * 4]) = v;
        }
#pragma unroll
        for (int i = 0; i < 4; i++) {
            int t = tid + i * 256;
            int r = t >> 4;
            int c4 = t & 15;
            float4 v = *reinterpret_cast<const float4*>(&W[(size_t)(k0 + r) * F_OUT + c4 * 4]);
            *reinterpret_cast<float4*>(&ws[r][c4 * 4]) = v;
        }
        __syncthreads();
#pragma unroll 16
        for (int k = 0; k < 64; k++) {
            float4 w = *reinterpret_cast<float4*>(&ws[k][tx * 4]);
            float x0 = xs[ty * 4 + 0][k];
            float x1 = xs[ty * 4 + 1][k];
            float x2 = xs[ty * 4 + 2][k];
            float x3 = xs[ty * 4 + 3][k];
            acc[0][0] += x0 * w.x; acc[0][1] += x0 * w.y; acc[0][2] += x0 * w.z; acc[0][3] += x0 * w.w;
            acc[1][0] += x1 * w.x; acc[1][1] += x1 * w.y; acc[1][2] += x1 * w.z; acc[1][3] += x1 * w.w;
            acc[2][0] += x2 * w.x; acc[2][1] += x2 * w.y; acc[2][2] += x2 * w.z; acc[2][3] += x2 * w.w;
            acc[3][0] += x3 * w.x; acc[3][1] += x3 * w.y; acc[3][2] += x3 * w.z; acc[3][3] += x3 * w.w;
        }
        __syncthreads();
    }
#pragma unroll
    for (int i = 0; i < 4; i++) {
        int gr = row0 + ty * 4 + i;
        if (gr < N) {
            float4 v = make_float4(acc[i][0], acc[i][1], acc[i][2], acc[i][3]);
            *reinterpret_cast<float4*>(&g_h2[(size_t)gr * F_OUT + tx * 4]) = v;
        }
    }
}

// ---------------------------------------------------------------------------
// 8. agg2: warp per dst row (64 floats -> float2 per lane), incl. self-loop.
// ---------------------------------------------------------------------------
__global__ void agg2_kernel(int N) {
    int lane = threadIdx.x & 31;
    int warp = (blockIdx.x * blockDim.x + threadIdx.x) >> 5;
    int nwarps = (gridDim.x * blockDim.x) >> 5;
    for (int r = warp; r < N; r += nwarps) {
        float dr = g_dinv[r];
        size_t rbase = (size_t)r * F_OUT + lane * 2;
        float2 acc = *reinterpret_cast<const float2*>(&g_h2[rbase]);
        float d2 = dr * dr;
        acc.x *= d2; acc.y *= d2;

        int beg = g_rowptr[r];
        int end = g_rowptr[r + 1];
        int e = beg;
        for (; e + 1 < end; e += 2) {
            int s0 = g_csrc[e];
            int s1 = g_csrc[e + 1];
            float n0 = g_dinv[s0] * dr;
            float n1 = g_dinv[s1] * dr;
            float2 v0 = *reinterpret_cast<const float2*>(&g_h2[(size_t)s0 * F_OUT + lane * 2]);
            float2 v1 = *reinterpret_cast<const float2*>(&g_h2[(size_t)s1 * F_OUT + lane * 2]);
            acc.x += v0.x * n0 + v1.x * n1;
            acc.y += v0.y * n0 + v1.y * n1;
        }
        if (e < end) {
            int s0 = g_csrc[e];
            float n0 = g_dinv[s0] * dr;
            float2 v0 = *reinterpret_cast<const float2*>(&g_h2[(size_t)s0 * F_OUT + lane * 2]);
            acc.x += v0.x * n0;
            acc.y += v0.y * n0;
        }
        *reinterpret_cast<float2*>(&g_a2[rbase]) = acc;
    }
}

// ---------------------------------------------------------------------------
// 9. finalize: out = log_softmax(a2 + b2)   (warp per row)
// ---------------------------------------------------------------------------
__global__ void finalize_kernel(const float* __restrict__ b2,
                                float* __restrict__ out, int N) {
    int lane = threadIdx.x & 31;
    int warp = (blockIdx.x * blockDim.x + threadIdx.x) >> 5;
    int nwarps = (gridDim.x * blockDim.x) >> 5;
    for (int r = warp; r < N; r += nwarps) {
        size_t base = (size_t)r * F_OUT;
        float v0 = g_a2[base + lane]      + b2[lane];
        float v1 = g_a2[base + lane + 32] + b2[lane + 32];
        float m = fmaxf(v0, v1);
#pragma unroll
        for (int o = 16; o; o >>= 1) m = fmaxf(m, __shfl_xor_sync(0xffffffffu, m, o));
        float s = __expf(v0 - m) + __expf(v1 - m);
#pragma unroll
        for (int o = 16; o; o >>= 1) s += __shfl_xor_sync(0xffffffffu, s, o);
        float lse = m + __logf(s);
        out[base + lane]      = v0 - lse;
        out[base + lane + 32] = v1 - lse;
    }
}

// ---------------------------------------------------------------------------
extern "C" void kernel_launch(void* const* d_in, const int* in_sizes, int n_in,
                              void* d_out, int out_size) {
    const float* x  = (const float*)d_in[0];
    const void*  ei = d_in[1];
    const float* W1 = (const float*)d_in[2];
    const float* b1 = (const float*)d_in[3];
    const float* W2 = (const float*)d_in[4];
    const float* b2 = (const float*)d_in[5];
    float* out = (float*)d_out;

    int N = in_sizes[0] / F_IN;     // 100000
    int E = in_sizes[1] / 2;        // 1600000
    if (N > NMAX) N = NMAX;
    if (E > EMAX) E = EMAX;

    detect_kernel<<<1, 32>>>((const int*)ei);
    zero_deg_kernel<<<(N + 255) / 256, 256>>>(N);
    edge_prep_kernel<<<2048, 256>>>(ei, E, N);
    scan_kernel<<<1, 1024>>>(N);
    csr_fill_kernel<<<2048, 256>>>(E);
    gemm1_kernel<<<dim3((N + 63) / 64, F_MID / 64), 256>>>(x, W1, N);
    agg1_kernel<<<(N * 32 + 255) / 256, 256>>>(N);
    gemm2_kernel<<<dim3((N + 63) / 64, 1), 256>>>(W2, b1, N);
    agg2_kernel<<<(N * 32 + 255) / 256, 256>>>(N);
    finalize_kernel<<<1024, 256>>>(b2, out, N);
}

// round 5
// speedup vs baseline: 1.6629x; 1.6629x over previous
#include <cuda_runtime.h>
#include <cuda_bf16.h>
#include <cstdint>

// ---------------------------------------------------------------------------
// SimpleGCN R5: CSR-gather aggregation + parallel 3-phase scan.
//
// R4 post-mortem: single-block scan_kernel took 228us (one SM, serial loops).
// R5 replaces it with: scan_local (per-block scan, block sums) ->
// scan_bsum (1 small block over 98 sums) -> scan_finalize (add offsets,
// write rowptr/cursor/dinv).
// ---------------------------------------------------------------------------

#define NMAX 100000
#define EMAX 1600000
#define F_IN 128
#define F_MID 128
#define F_OUT 64

#define SCAN_CHUNK 1024
#define NBLK_SCAN ((NMAX + SCAN_CHUNK - 1) / SCAN_CHUNK)   // 98

__device__ __align__(16) int   g_src[EMAX];
__device__ __align__(16) int   g_dst[EMAX];
__device__ __align__(16) int   g_csrc[EMAX];
__device__ __align__(16) int   g_deg[NMAX];
__device__ __align__(16) int   g_rowptr[NMAX + 1];
__device__ __align__(16) int   g_cursor[NMAX];
__device__ __align__(16) int   g_bsum[NBLK_SCAN];
__device__ __align__(16) int   g_boff[NBLK_SCAN];
__device__ __align__(16) float g_dinv[NMAX];
__device__ __align__(16) float g_h1[(size_t)NMAX * F_MID];
__device__ __align__(16) float g_a1[(size_t)NMAX * F_MID];
__device__ __align__(16) float g_h2[(size_t)NMAX * F_OUT];
__device__ __align__(16) float g_a2[(size_t)NMAX * F_OUT];
__device__ int g_is64;

// ---------------------------------------------------------------------------
// 0. dtype detect: int64 node ids < 2^31 -> every odd int32 word is zero.
// ---------------------------------------------------------------------------
__global__ void detect_kernel(const int* __restrict__ ei32) {
    if (threadIdx.x == 0 && blockIdx.x == 0) {
        int allzero = 1;
        for (int i = 0; i < 64; i++)
            if (ei32[2 * i + 1] != 0) { allzero = 0; break; }
        g_is64 = allzero;
    }
}

// ---------------------------------------------------------------------------
// 1. zero deg
// ---------------------------------------------------------------------------
__global__ void zero_deg_kernel(int N) {
    int i = blockIdx.x * blockDim.x + threadIdx.x;
    if (i < N) g_deg[i] = 0;
}

// ---------------------------------------------------------------------------
// 2. edge decode + degree histogram
// ---------------------------------------------------------------------------
__global__ void edge_prep_kernel(const void* __restrict__ ei_raw, int E, int N) {
    const int is64 = g_is64;
    const int stride = gridDim.x * blockDim.x;
    const int* __restrict__ p32 = (const int*)ei_raw;
    const long long* __restrict__ p64 = (const long long*)ei_raw;
    for (int e = blockIdx.x * blockDim.x + threadIdx.x; e < E; e += stride) {
        int s, d;
        if (is64) {
            s = (int)p64[e];
            d = (int)p64[(size_t)E + e];
        } else {
            s = p32[e];
            d = p32[(size_t)E + e];
        }
        s = min(max(s, 0), N - 1);
        d = min(max(d, 0), N - 1);
        g_src[e] = s;
        g_dst[e] = d;
        atomicAdd(&g_deg[d], 1);
    }
}

// ---------------------------------------------------------------------------
// 3a. per-block exclusive scan of deg chunk; block sum out.
// ---------------------------------------------------------------------------
__global__ void scan_local_kernel(int N) {
    __shared__ int sh[SCAN_CHUNK];
    int tid = threadIdx.x;
    int gi = blockIdx.x * SCAN_CHUNK + tid;
    int v = (gi < N) ? g_deg[gi] : 0;
    sh[tid] = v;
    __syncthreads();
    // inclusive Hillis-Steele over 1024
    for (int off = 1; off < SCAN_CHUNK; off <<= 1) {
        int t = 0;
        if (tid >= off) t = sh[tid - off];
        __syncthreads();
        if (tid >= off) sh[tid] += t;
        __syncthreads();
    }
    if (gi < N) g_rowptr[gi] = sh[tid] - v;          // exclusive, local
    if (tid == SCAN_CHUNK - 1) g_bsum[blockIdx.x] = sh[tid];
}

// ---------------------------------------------------------------------------
// 3b. scan the 98 block sums (single tiny block).
// ---------------------------------------------------------------------------
__global__ void scan_bsum_kernel(int nblk, int N) {
    __shared__ int sh[128];
    int tid = threadIdx.x;
    int v = (tid < nblk) ? g_bsum[tid] : 0;
    sh[tid] = v;
    __syncthreads();
    for (int off = 1; off < 128; off <<= 1) {
        int t = 0;
        if (tid >= off) t = sh[tid - off];
        __syncthreads();
        if (tid >= off) sh[tid] += t;
        __syncthreads();
    }
    if (tid < nblk) g_boff[tid] = sh[tid] - v;       // exclusive
    if (tid == 127) g_rowptr[N] = sh[127];           // total = E
}

// ---------------------------------------------------------------------------
// 3c. add block offsets; write cursor + dinv.
// ---------------------------------------------------------------------------
__global__ void scan_finalize_kernel(int N) {
    int gi = blockIdx.x * blockDim.x + threadIdx.x;
    if (gi < N) {
        int rp = g_rowptr[gi] + g_boff[gi / SCAN_CHUNK];
        g_rowptr[gi] = rp;
        g_cursor[gi] = rp;
        g_dinv[gi] = rsqrtf((float)(g_deg[gi] + 1));
    }
}

// ---------------------------------------------------------------------------
// 4. counting-sort fill: csr_src grouped by dst
// ---------------------------------------------------------------------------
__global__ void csr_fill_kernel(int E) {
    int stride = gridDim.x * blockDim.x;
    for (int e = blockIdx.x * blockDim.x + threadIdx.x; e < E; e += stride) {
        int d = g_dst[e];
        int pos = atomicAdd(&g_cursor[d], 1);
        g_csrc[pos] = g_src[e];
    }
}

// ---------------------------------------------------------------------------
// 5. GEMM1: g_h1 = x @ W1   (N x 128) @ (128 x 128)
// ---------------------------------------------------------------------------
__global__ void gemm1_kernel(const float* __restrict__ X,
                             const float* __restrict__ W, int N) {
    __shared__ float xs[64][64];
    __shared__ float ws[64][64];
    int tid = threadIdx.x;
    int tx = tid & 15;
    int ty = tid >> 4;
    int row0 = blockIdx.x * 64;
    int col0 = blockIdx.y * 64;

    float acc[4][4];
#pragma unroll
    for (int i = 0; i < 4; i++)
#pragma unroll
        for (int j = 0; j < 4; j++) acc[i][j] = 0.f;

    for (int k0 = 0; k0 < F_IN; k0 += 64) {
#pragma unroll
        for (int i = 0; i < 4; i++) {
            int t = tid + i * 256;
            int r = t >> 4;
            int c4 = t & 15;
            float4 v = make_float4(0.f, 0.f, 0.f, 0.f);
            int gr = row0 + r;
            if (gr < N)
                v = *reinterpret_cast<const float4*>(&X[(size_t)gr * F_IN + k0 + c4 * 4]);
            *reinterpret_cast<float4*>(&xs[r][c4 * 4]) = v;
        }
#pragma unroll
        for (int i = 0; i < 4; i++) {
            int t = tid + i * 256;
            int r = t >> 4;
            int c4 = t & 15;
            float4 v = *reinterpret_cast<const float4*>(&W[(size_t)(k0 + r) * F_MID + col0 + c4 * 4]);
            *reinterpret_cast<float4*>(&ws[r][c4 * 4]) = v;
        }
        __syncthreads();
#pragma unroll 16
        for (int k = 0; k < 64; k++) {
            float4 w = *reinterpret_cast<float4*>(&ws[k][tx * 4]);
            float x0 = xs[ty * 4 + 0][k];
            float x1 = xs[ty * 4 + 1][k];
            float x2 = xs[ty * 4 + 2][k];
            float x3 = xs[ty * 4 + 3][k];
            acc[0][0] += x0 * w.x; acc[0][1] += x0 * w.y; acc[0][2] += x0 * w.z; acc[0][3] += x0 * w.w;
            acc[1][0] += x1 * w.x; acc[1][1] += x1 * w.y; acc[1][2] += x1 * w.z; acc[1][3] += x1 * w.w;
            acc[2][0] += x2 * w.x; acc[2][1] += x2 * w.y; acc[2][2] += x2 * w.z; acc[2][3] += x2 * w.w;
            acc[3][0] += x3 * w.x; acc[3][1] += x3 * w.y; acc[3][2] += x3 * w.z; acc[3][3] += x3 * w.w;
        }
        __syncthreads();
    }
#pragma unroll
    for (int i = 0; i < 4; i++) {
        int gr = row0 + ty * 4 + i;
        if (gr < N) {
            float4 v = make_float4(acc[i][0], acc[i][1], acc[i][2], acc[i][3]);
            *reinterpret_cast<float4*>(&g_h1[(size_t)gr * F_MID + col0 + tx * 4]) = v;
        }
    }
}

// ---------------------------------------------------------------------------
// 6. agg1: warp per dst row, register accumulation, includes self-loop.
// ---------------------------------------------------------------------------
__global__ void agg1_kernel(int N) {
    int lane = threadIdx.x & 31;
    int warp = (blockIdx.x * blockDim.x + threadIdx.x) >> 5;
    int nwarps = (gridDim.x * blockDim.x) >> 5;
    for (int r = warp; r < N; r += nwarps) {
        float dr = g_dinv[r];
        size_t rbase = (size_t)r * F_MID + lane * 4;
        float4 acc = *reinterpret_cast<const float4*>(&g_h1[rbase]);
        float d2 = dr * dr;
        acc.x *= d2; acc.y *= d2; acc.z *= d2; acc.w *= d2;

        int beg = g_rowptr[r];
        int end = g_rowptr[r + 1];
        int e = beg;
        for (; e + 1 < end; e += 2) {
            int s0 = g_csrc[e];
            int s1 = g_csrc[e + 1];
            float n0 = g_dinv[s0] * dr;
            float n1 = g_dinv[s1] * dr;
            float4 v0 = *reinterpret_cast<const float4*>(&g_h1[(size_t)s0 * F_MID + lane * 4]);
            float4 v1 = *reinterpret_cast<const float4*>(&g_h1[(size_t)s1 * F_MID + lane * 4]);
            acc.x += v0.x * n0 + v1.x * n1;
            acc.y += v0.y * n0 + v1.y * n1;
            acc.z += v0.z * n0 + v1.z * n1;
            acc.w += v0.w * n0 + v1.w * n1;
        }
        if (e < end) {
            int s0 = g_csrc[e];
            float n0 = g_dinv[s0] * dr;
            float4 v0 = *reinterpret_cast<const float4*>(&g_h1[(size_t)s0 * F_MID + lane * 4]);
            acc.x += v0.x * n0;
            acc.y += v0.y * n0;
            acc.z += v0.z * n0;
            acc.w += v0.w * n0;
        }
        *reinterpret_cast<float4*>(&g_a1[rbase]) = acc;
    }
}

// ---------------------------------------------------------------------------
// 7. GEMM2: g_h2 = relu(a1 + b1) @ W2
// ---------------------------------------------------------------------------
__global__ void gemm2_kernel(const float* __restrict__ W,
                             const float* __restrict__ b1, int N) {
    __shared__ float xs[64][64];
    __shared__ float ws[64][64];
    int tid = threadIdx.x;
    int tx = tid & 15;
    int ty = tid >> 4;
    int row0 = blockIdx.x * 64;

    float acc[4][4];
#pragma unroll
    for (int i = 0; i < 4; i++)
#pragma unroll
        for (int j = 0; j < 4; j++) acc[i][j] = 0.f;

    for (int k0 = 0; k0 < F_MID; k0 += 64) {
#pragma unroll
        for (int i = 0; i < 4; i++) {
            int t = tid + i * 256;
            int r = t >> 4;
            int c4 = t & 15;
            float4 v = make_float4(0.f, 0.f, 0.f, 0.f);
            int gr = row0 + r;
            if (gr < N) {
                size_t off = (size_t)gr * F_MID + k0 + c4 * 4;
                float4 a = *reinterpret_cast<const float4*>(&g_a1[off]);
                float4 b = *reinterpret_cast<const float4*>(&b1[k0 + c4 * 4]);
                v.x = fmaxf(a.x + b.x, 0.f);
                v.y = fmaxf(a.y + b.y, 0.f);
                v.z = fmaxf(a.z + b.z, 0.f);
                v.w = fmaxf(a.w + b.w, 0.f);
            }
            *reinterpret_cast<float4*>(&xs[r][c4 * 4]) = v;
        }
#pragma unroll
        for (int i = 0; i < 4; i++) {
            int t = tid + i * 256;
            int r = t >> 4;
            int c4 = t & 15;
            float4 v = *reinterpret_cast<const float4*>(&W[(size_t)(k0 + r) * F_OUT + c4 * 4]);
            *reinterpret_cast<float4*>(&ws[r][c4 * 4]) = v;
        }
        __syncthreads();
#pragma unroll 16
        for (int k = 0; k < 64; k++) {
            float4 w = *reinterpret_cast<float4*>(&ws[k][tx * 4]);
            float x0 = xs[ty * 4 + 0][k];
            float x1 = xs[ty * 4 + 1][k];
            float x2 = xs[ty * 4 + 2][k];
            float x3 = xs[ty * 4 + 3][k];
            acc[0][0] += x0 * w.x; acc[0][1] += x0 * w.y; acc[0][2] += x0 * w.z; acc[0][3] += x0 * w.w;
            acc[1][0] += x1 * w.x; acc[1][1] += x1 * w.y; acc[1][2] += x1 * w.z; acc[1][3] += x1 * w.w;
            acc[2][0] += x2 * w.x; acc[2][1] += x2 * w.y; acc[2][2] += x2 * w.z; acc[2][3] += x2 * w.w;
            acc[3][0] += x3 * w.x; acc[3][1] += x3 * w.y; acc[3][2] += x3 * w.z; acc[3][3] += x3 * w.w;
        }
        __syncthreads();
    }
#pragma unroll
    for (int i = 0; i < 4; i++) {
        int gr = row0 + ty * 4 + i;
        if (gr < N) {
            float4 v = make_float4(acc[i][0], acc[i][1], acc[i][2], acc[i][3]);
            *reinterpret_cast<float4*>(&g_h2[(size_t)gr * F_OUT + tx * 4]) = v;
        }
    }
}

// ---------------------------------------------------------------------------
// 8. agg2: warp per dst row (float2 per lane), incl. self-loop.
// ---------------------------------------------------------------------------
__global__ void agg2_kernel(int N) {
    int lane = threadIdx.x & 31;
    int warp = (blockIdx.x * blockDim.x + threadIdx.x) >> 5;
    int nwarps = (gridDim.x * blockDim.x) >> 5;
    for (int r = warp; r < N; r += nwarps) {
        float dr = g_dinv[r];
        size_t rbase = (size_t)r * F_OUT + lane * 2;
        float2 acc = *reinterpret_cast<const float2*>(&g_h2[rbase]);
        float d2 = dr * dr;
        acc.x *= d2; acc.y *= d2;

        int beg = g_rowptr[r];
        int end = g_rowptr[r + 1];
        int e = beg;
        for (; e + 1 < end; e += 2) {
            int s0 = g_csrc[e];
            int s1 = g_csrc[e + 1];
            float n0 = g_dinv[s0] * dr;
            float n1 = g_dinv[s1] * dr;
            float2 v0 = *reinterpret_cast<const float2*>(&g_h2[(size_t)s0 * F_OUT + lane * 2]);
            float2 v1 = *reinterpret_cast<const float2*>(&g_h2[(size_t)s1 * F_OUT + lane * 2]);
            acc.x += v0.x * n0 + v1.x * n1;
            acc.y += v0.y * n0 + v1.y * n1;
        }
        if (e < end) {
            int s0 = g_csrc[e];
            float n0 = g_dinv[s0] * dr;
            float2 v0 = *reinterpret_cast<const float2*>(&g_h2[(size_t)s0 * F_OUT + lane * 2]);
            acc.x += v0.x * n0;
            acc.y += v0.y * n0;
        }
        *reinterpret_cast<float2*>(&g_a2[rbase]) = acc;
    }
}

// ---------------------------------------------------------------------------
// 9. finalize: out = log_softmax(a2 + b2)   (warp per row)
// ---------------------------------------------------------------------------
__global__ void finalize_kernel(const float* __restrict__ b2,
                                float* __restrict__ out, int N) {
    int lane = threadIdx.x & 31;
    int warp = (blockIdx.x * blockDim.x + threadIdx.x) >> 5;
    int nwarps = (gridDim.x * blockDim.x) >> 5;
    for (int r = warp; r < N; r += nwarps) {
        size_t base = (size_t)r * F_OUT;
        float v0 = g_a2[base + lane]      + b2[lane];
        float v1 = g_a2[base + lane + 32] + b2[lane + 32];
        float m = fmaxf(v0, v1);
#pragma unroll
        for (int o = 16; o; o >>= 1) m = fmaxf(m, __shfl_xor_sync(0xffffffffu, m, o));
        float s = __expf(v0 - m) + __expf(v1 - m);
#pragma unroll
        for (int o = 16; o; o >>= 1) s += __shfl_xor_sync(0xffffffffu, s, o);
        float lse = m + __logf(s);
        out[base + lane]      = v0 - lse;
        out[base + lane + 32] = v1 - lse;
    }
}

// ---------------------------------------------------------------------------
extern "C" void kernel_launch(void* const* d_in, const int* in_sizes, int n_in,
                              void* d_out, int out_size) {
    const float* x  = (const float*)d_in[0];
    const void*  ei = d_in[1];
    const float* W1 = (const float*)d_in[2];
    const float* b1 = (const float*)d_in[3];
    const float* W2 = (const float*)d_in[4];
    const float* b2 = (const float*)d_in[5];
    float* out = (float*)d_out;

    int N = in_sizes[0] / F_IN;     // 100000
    int E = in_sizes[1] / 2;        // 1600000
    if (N > NMAX) N = NMAX;
    if (E > EMAX) E = EMAX;

    int nblk_scan = (N + SCAN_CHUNK - 1) / SCAN_CHUNK;

    detect_kernel<<<1, 32>>>((const int*)ei);
    zero_deg_kernel<<<(N + 255) / 256, 256>>>(N);
    edge_prep_kernel<<<2048, 256>>>(ei, E, N);
    scan_local_kernel<<<nblk_scan, SCAN_CHUNK>>>(N);
    scan_bsum_kernel<<<1, 128>>>(nblk_scan, N);
    scan_finalize_kernel<<<(N + 255) / 256, 256>>>(N);
    csr_fill_kernel<<<2048, 256>>>(E);
    gemm1_kernel<<<dim3((N + 63) / 64, F_MID / 64), 256>>>(x, W1, N);
    agg1_kernel<<<(N * 32 + 255) / 256, 256>>>(N);
    gemm2_kernel<<<dim3((N + 63) / 64, 1), 256>>>(W2, b1, N);
    agg2_kernel<<<(N * 32 + 255) / 256, 256>>>(N);
    finalize_kernel<<<1024, 256>>>(b2, out, N);
}